// round 16
// baseline (speedup 1.0000x reference)
#include <cuda_runtime.h>
#include <cuda_fp16.h>
#include <cstdint>
#include <cstddef>
#include <math.h>

// Problem constants
constexpr int NB  = 4;
constexpr int NS  = 2048;
constexpr int NDV = 1024;
constexpr int NH  = 16;
constexpr int NDH = 64;
constexpr int NT  = 64;
constexpr int NDT = 768;

// Scratch (device globals: allocation-free rule)
__device__ float  g_pool[NB * NDT];
__device__ float  g_gate_q[NB * NDV];
__device__ float  g_gate_k[NB * NDV];
__device__ __half g_wt[(size_t)3 * NDV * NDV];        // [z][nout][k] fp16
__device__ __half g_hidh[(size_t)NB * NS * NDV];      // hid as fp16
__device__ __half g_q[(size_t)NB * NH * NS * NDH];    // [bh][s][d]
__device__ __half g_k[(size_t)NB * NH * NS * NDH];    // [bh][s][d]
__device__ __half g_v[(size_t)NB * NH * NS * NDH];    // [bh][d][s] (TRANSPOSED)

// ---------------------------------------------------------------------------
// helpers
// ---------------------------------------------------------------------------
__device__ __forceinline__ void cp_async16(void* smem_dst, const void* gmem_src) {
    unsigned int s = (unsigned int)__cvta_generic_to_shared(smem_dst);
    asm volatile("cp.async.cg.shared.global [%0], [%1], 16;\n" :: "r"(s), "l"(gmem_src));
}
__device__ __forceinline__ void cp_commit() {
    asm volatile("cp.async.commit_group;\n");
}
template <int N>
__device__ __forceinline__ void cp_wait() {
    asm volatile("cp.async.wait_group %0;\n" :: "n"(N));
}
// D += A*B, m16n8k16 fp16 -> f32
__device__ __forceinline__ void mma_f16(float* c, const unsigned* a,
                                        unsigned b0, unsigned b1) {
    asm volatile(
        "mma.sync.aligned.m16n8k16.row.col.f32.f16.f16.f32 "
        "{%0,%1,%2,%3}, {%4,%5,%6,%7}, {%8,%9}, {%0,%1,%2,%3};\n"
        : "+f"(c[0]), "+f"(c[1]), "+f"(c[2]), "+f"(c[3])
        : "r"(a[0]), "r"(a[1]), "r"(a[2]), "r"(a[3]), "r"(b0), "r"(b1));
}
// ldmatrix x4 (b16)
__device__ __forceinline__ void ldsm_x4(unsigned* r, const void* p) {
    unsigned addr = (unsigned)__cvta_generic_to_shared(p);
    asm volatile("ldmatrix.sync.aligned.m8n8.x4.shared.b16 {%0,%1,%2,%3}, [%4];"
                 : "=r"(r[0]), "=r"(r[1]), "=r"(r[2]), "=r"(r[3]) : "r"(addr));
}
__device__ __forceinline__ unsigned pack_h2(float lo, float hi) {
    __half2 h = __floats2half2_rn(lo, hi);
    return *(unsigned*)&h;
}

// ---------------------------------------------------------------------------
// Kernel 0a: weight transpose+convert  g_wt[z][n][k] = fp16(W_z[k][n])
// ---------------------------------------------------------------------------
__global__ void wt_kernel(const float* __restrict__ Wq,
                          const float* __restrict__ Wk,
                          const float* __restrict__ Wv) {
    __shared__ float t[32][33];
    int z = blockIdx.z;
    const float* W = (z == 0) ? Wq : (z == 1) ? Wk : Wv;
    __half* out = g_wt + (size_t)z * NDV * NDV;
    int k0 = blockIdx.x * 32, n0 = blockIdx.y * 32;
    int x = threadIdx.x, y = threadIdx.y;       // 32 x 8
#pragma unroll
    for (int i = 0; i < 32; i += 8)
        t[y + i][x] = W[(size_t)(k0 + y + i) * NDV + n0 + x];
    __syncthreads();
#pragma unroll
    for (int i = 0; i < 32; i += 8)
        out[(size_t)(n0 + y + i) * NDV + k0 + x] = __float2half(t[x][y + i]);
}

// ---------------------------------------------------------------------------
// Kernel 0b: hid -> fp16
// ---------------------------------------------------------------------------
__global__ void hidh_kernel(const float* __restrict__ hid) {
    size_t i = ((size_t)blockIdx.x * blockDim.x + threadIdx.x) * 4;
    if (i >= (size_t)NB * NS * NDV) return;
    float4 v = *(const float4*)&hid[i];
    __half2 lo = __floats2half2_rn(v.x, v.y);
    __half2 hi = __floats2half2_rn(v.z, v.w);
    *(__half2*)&g_hidh[i]     = lo;
    *(__half2*)&g_hidh[i + 2] = hi;
}

// ---------------------------------------------------------------------------
// Kernel 1: masked-mean pool over text tokens.  pool[b,d]
// ---------------------------------------------------------------------------
__global__ void pool_kernel(const float* __restrict__ txt,
                            const float* __restrict__ tmask) {
    int i = blockIdx.x * blockDim.x + threadIdx.x;
    if (i >= NB * NDT) return;
    int b = i / NDT;
    int d = i - b * NDT;
    float s = 0.f, ms = 0.f;
#pragma unroll 8
    for (int t = 0; t < NT; ++t) {
        float mv = tmask[b * NT + t];
        s += txt[((size_t)(b * NT + t)) * NDT + d] * mv;
        ms += mv;
    }
    g_pool[i] = s / ms;
}

// ---------------------------------------------------------------------------
// Kernel 2: gates = 1 + sigmoid(pool @ Wd + bd).  (R15 parallel version)
// ---------------------------------------------------------------------------
__global__ void __launch_bounds__(256) gate_kernel(
        const float* __restrict__ Wdq, const float* __restrict__ bdq,
        const float* __restrict__ Wdk, const float* __restrict__ bdk) {
    __shared__ float ps[NDT];
    __shared__ float red[16][64];

    int bx    = blockIdx.x;
    int which = blockIdx.y;
    int b     = blockIdx.z;
    const float* W  = which ? Wdk : Wdq;
    const float* bb = which ? bdk : bdq;
    int tid = threadIdx.x;

    for (int i = tid; i < NDT; i += 256)
        ps[i] = g_pool[b * NDT + i];
    __syncthreads();

    int nq = tid & 15;
    int g  = tid >> 4;
    int n  = bx * 64 + nq * 4;
    float4 acc = make_float4(0.f, 0.f, 0.f, 0.f);
    int d0 = g * 48;
#pragma unroll 8
    for (int d = d0; d < d0 + 48; ++d) {
        float p = ps[d];
        float4 wv = *(const float4*)&W[(size_t)d * NDV + n];
        acc.x += p * wv.x; acc.y += p * wv.y;
        acc.z += p * wv.z; acc.w += p * wv.w;
    }
    *(float4*)&red[g][nq * 4] = acc;
    __syncthreads();

    if (tid < 64) {
        float s = 0.f;
#pragma unroll
        for (int g2 = 0; g2 < 16; ++g2) s += red[g2][tid];
        int col = bx * 64 + tid;
        float gate = 1.f + 1.f / (1.f + expf(-(s + bb[col])));
        (which ? g_gate_k : g_gate_q)[b * NDV + col] = gate;
    }
}

// ---------------------------------------------------------------------------
// Kernel 3: QKV projection via fp16 m16n8k16 mma + ldmatrix.  (unchanged)
// ---------------------------------------------------------------------------
constexpr int QKC  = 32;
constexpr int QPT  = 40;
constexpr int QNIT = NDV / QKC;
constexpr int QSTG = 3;
constexpr int QTILE = 128 * QPT;
constexpr int QKV_SMEM_BYTES = QSTG * 2 * QTILE * 2;   // 61440

__global__ void __launch_bounds__(256, 2) qkv_kernel(
        const float* __restrict__ bq,
        const float* __restrict__ bk,
        const float* __restrict__ bv) {
    extern __shared__ __half qsm[];
    __half* As = qsm;
    __half* Bs = qsm + QSTG * QTILE;

    int z = blockIdx.z;
    const __half* Wt = g_wt + (size_t)z * NDV * NDV;
    const float* bias = (z == 0) ? bq : (z == 1) ? bk : bv;
    const float* gate = (z == 0) ? g_gate_q : (z == 1) ? g_gate_k : nullptr;
    __half* out = (z == 0) ? g_q : (z == 1) ? g_k : g_v;

    int m0 = blockIdx.y * 128;
    int n0 = blockIdx.x * 128;
    int tid  = threadIdx.x;
    int warp = tid >> 5;
    int lane = tid & 31;
    int gid  = lane >> 2;
    int tig  = lane & 3;
    int wm = warp & 3;
    int wn = warp >> 2;
    int l16 = lane & 15;
    int l8  = lane & 7;
    int ahh = (lane >> 4) * 8;
    int brow8 = ((lane >> 4) & 1) * 8;
    int bk8   = ((lane >> 3) & 1) * 8;

    auto issue = [&](int c, int st) {
#pragma unroll
        for (int u = 0; u < 2; ++u) {
            int idx = tid * 2 + u;
            int row = idx >> 2;
            int c16 = idx & 3;
            cp_async16(&As[(size_t)st * QTILE + row * QPT + c16 * 8],
                       &g_hidh[(size_t)(m0 + row) * NDV + c * QKC + c16 * 8]);
            cp_async16(&Bs[(size_t)st * QTILE + row * QPT + c16 * 8],
                       &Wt[(size_t)(n0 + row) * NDV + c * QKC + c16 * 8]);
        }
        cp_commit();
    };

    float c[2][8][4];
#pragma unroll
    for (int mt = 0; mt < 2; ++mt)
#pragma unroll
        for (int nt = 0; nt < 8; ++nt)
#pragma unroll
            for (int r = 0; r < 4; ++r) c[mt][nt][r] = 0.f;

    issue(0, 0);
    issue(1, 1);

    int st = 0;
    for (int it = 0; it < QNIT; ++it) {
        cp_wait<1>();
        __syncthreads();
        int st2 = st + 2; if (st2 >= QSTG) st2 -= QSTG;
        if (it + 2 < QNIT) issue(it + 2, st2);

        const __half* Ap = &As[(size_t)st * QTILE];
        const __half* Bp = &Bs[(size_t)st * QTILE];

        unsigned a[2][2][4];
#pragma unroll
        for (int mt = 0; mt < 2; ++mt)
#pragma unroll
            for (int ks = 0; ks < 2; ++ks)
                ldsm_x4(a[mt][ks],
                        &Ap[(wm * 32 + mt * 16 + l16) * QPT + ks * 16 + ahh]);

        unsigned bfr[4][2][4];
#pragma unroll
        for (int ntp = 0; ntp < 4; ++ntp)
#pragma unroll
            for (int ks = 0; ks < 2; ++ks)
                ldsm_x4(bfr[ntp][ks],
                        &Bp[(wn * 64 + ntp * 16 + brow8 + l8) * QPT + ks * 16 + bk8]);

#pragma unroll
        for (int mt = 0; mt < 2; ++mt)
#pragma unroll
            for (int ntp = 0; ntp < 4; ++ntp)
#pragma unroll
                for (int ks = 0; ks < 2; ++ks) {
                    mma_f16(c[mt][2 * ntp],     a[mt][ks], bfr[ntp][ks][0], bfr[ntp][ks][1]);
                    mma_f16(c[mt][2 * ntp + 1], a[mt][ks], bfr[ntp][ks][2], bfr[ntp][ks][3]);
                }

        if (++st == QSTG) st = 0;
    }

    int b = m0 >> 11;
#pragma unroll
    for (int mt = 0; mt < 2; ++mt) {
        int tok  = m0 + wm * 32 + mt * 16 + gid;
        int srow = tok & (NS - 1);
#pragma unroll
        for (int nt = 0; nt < 8; ++nt) {
            int col = n0 + wn * 64 + nt * 8 + 2 * tig;
            float g0 = gate ? gate[b * NDV + col]     : 1.f;
            float g1 = gate ? gate[b * NDV + col + 1] : 1.f;
            float b0v = bias[col], b1v = bias[col + 1];
            float v00 = (c[mt][nt][0] + b0v) * g0;
            float v01 = (c[mt][nt][1] + b1v) * g1;
            float v10 = (c[mt][nt][2] + b0v) * g0;
            float v11 = (c[mt][nt][3] + b1v) * g1;
            int h = col >> 6, d = col & 63;
            if (z == 2) {
                __half* p = out + ((size_t)(b * NH + h) * NDH + d) * NS;
                p[srow]          = __float2half(v00);
                p[NS + srow]     = __float2half(v01);
                p[srow + 8]      = __float2half(v10);
                p[NS + srow + 8] = __float2half(v11);
            } else {
                __half* p = out + ((size_t)(b * NH + h) * NS) * NDH + d;
                *(__half2*)&p[(size_t)srow * NDH] = __floats2half2_rn(v00, v01);
                *(__half2*)&p[(size_t)(srow + 8) * NDH] = __floats2half2_rn(v10, v11);
            }
        }
    }
}

// ---------------------------------------------------------------------------
// Kernel 4: flash attention, fp16 m16n8k16, BK=128 (2x keys per iteration:
// half the softmax dependency chains and barriers).  BQ=64, 4 warps.
// Q frags from gmem; P C-frag pairs ARE the PV A-frags.  2-stage cp.async.
// ---------------------------------------------------------------------------
constexpr int BQ = 64;
constexpr int BK = 128;
constexpr int NTILE = NS / BK;          // 16
constexpr int KP  = 72;                 // K row pitch (64 halves + pad)
constexpr int VP2 = 136;                // V^T row pitch (128 halves + pad)
constexpr int ATTN_SMEM_BYTES = (2 * BK * KP + 2 * NDH * VP2) * 2;   // 71680

__global__ void __launch_bounds__(128, 3) attn_kernel(
        const float* __restrict__ amask, float* __restrict__ out) {
    extern __shared__ __half hsm[];
    __half* Ks = hsm;                         // [2][BK][KP]   token-major
    __half* Vs = hsm + 2 * BK * KP;           // [2][NDH][VP2] d-major (V^T)

    int bh = blockIdx.y;
    int b  = bh >> 4;
    int h  = bh & 15;
    int q0 = blockIdx.x * BQ;
    int tid  = threadIdx.x;
    int w    = tid >> 5;
    int lane = tid & 31;
    int gid  = lane >> 2;
    int tig  = lane & 3;
    int l8  = lane & 7;
    int brow8 = ((lane >> 4) & 1) * 8;
    int bk8   = ((lane >> 3) & 1) * 8;

    const __half* Qg = g_q + (size_t)bh * NS * NDH;
    const __half* Kg = g_k + (size_t)bh * NS * NDH;
    const __half* Vg = g_v + (size_t)bh * NDH * NS;   // [d][s]

    auto issue_kv = [&](int t0, int st) {
#pragma unroll
        for (int u = 0; u < 16; ++u) {
            int idx = tid + u * 128;          // 0..2047
            if (idx < 1024) {
                // K: 128 rows x 8 chunks of 16B
                int row = idx >> 3;
                int c16 = idx & 7;
                cp_async16(&Ks[(size_t)st * BK * KP + row * KP + c16 * 8],
                           &Kg[(size_t)(t0 + row) * NDH + c16 * 8]);
            } else {
                // V^T: 64 rows x 16 chunks of 16B
                int i2  = idx - 1024;
                int row = i2 >> 4;
                int c16 = i2 & 15;
                cp_async16(&Vs[(size_t)st * NDH * VP2 + row * VP2 + c16 * 8],
                           &Vg[(size_t)row * NS + t0 + c16 * 8]);
            }
        }
        cp_commit();
    };

    issue_kv(0, 0);

    // Q A-frags from gmem fp16 (4 k-chunks of 16)
    unsigned a[4][4];
    {
        const __half* Qr0 = Qg + (size_t)(q0 + w * 16 + gid) * NDH;
        const __half* Qr8 = Qr0 + 8 * NDH;
#pragma unroll
        for (int kc = 0; kc < 4; ++kc) {
            a[kc][0] = *(const unsigned*)&Qr0[kc * 16 + 2 * tig];
            a[kc][1] = *(const unsigned*)&Qr8[kc * 16 + 2 * tig];
            a[kc][2] = *(const unsigned*)&Qr0[kc * 16 + 8 + 2 * tig];
            a[kc][3] = *(const unsigned*)&Qr8[kc * 16 + 8 + 2 * tig];
        }
    }

    float o[8][4];
#pragma unroll
    for (int j = 0; j < 8; ++j)
#pragma unroll
        for (int r = 0; r < 4; ++r) o[j][r] = 0.f;
    float mrow[2] = {-1e30f, -1e30f};
    float lrow[2] = {0.f, 0.f};

    for (int it = 0; it < NTILE; ++it) {
        cp_wait<0>();
        __syncthreads();
        if (it + 1 < NTILE) issue_kv((it + 1) * BK, (it + 1) & 1);
        int st = it & 1;
        const __half* Kp = &Ks[(size_t)st * BK * KP];
        const __half* Vp = &Vs[(size_t)st * NDH * VP2];
        int t0 = it * BK;

        // S = Q @ K^T over 16 n-tiles (128 keys)
        float s[16][4];
#pragma unroll
        for (int nt = 0; nt < 16; ++nt)
            s[nt][0] = s[nt][1] = s[nt][2] = s[nt][3] = 0.f;
#pragma unroll
        for (int ntp = 0; ntp < 8; ++ntp)
#pragma unroll
            for (int kc = 0; kc < 4; ++kc) {
                unsigned bf[4];
                ldsm_x4(bf, &Kp[(ntp * 16 + brow8 + l8) * KP + kc * 16 + bk8]);
                mma_f16(s[2 * ntp],     a[kc], bf[0], bf[1]);
                mma_f16(s[2 * ntp + 1], a[kc], bf[2], bf[3]);
            }

        // scale + mask + ONE softmax pass over all 128 keys
        float mt0 = -1e30f, mt1 = -1e30f;
#pragma unroll
        for (int nt = 0; nt < 16; ++nt) {
            float2 mk = *(const float2*)&amask[b * NS + t0 + nt * 8 + 2 * tig];
            s[nt][0] = fmaf(s[nt][0], 0.125f, mk.x);
            s[nt][1] = fmaf(s[nt][1], 0.125f, mk.y);
            s[nt][2] = fmaf(s[nt][2], 0.125f, mk.x);
            s[nt][3] = fmaf(s[nt][3], 0.125f, mk.y);
            mt0 = fmaxf(mt0, fmaxf(s[nt][0], s[nt][1]));
            mt1 = fmaxf(mt1, fmaxf(s[nt][2], s[nt][3]));
        }
        mt0 = fmaxf(mt0, __shfl_xor_sync(0xffffffffu, mt0, 1));
        mt0 = fmaxf(mt0, __shfl_xor_sync(0xffffffffu, mt0, 2));
        mt1 = fmaxf(mt1, __shfl_xor_sync(0xffffffffu, mt1, 1));
        mt1 = fmaxf(mt1, __shfl_xor_sync(0xffffffffu, mt1, 2));

        float mn0 = fmaxf(mrow[0], mt0);
        float mn1 = fmaxf(mrow[1], mt1);
        float al0 = __expf(mrow[0] - mn0);
        float al1 = __expf(mrow[1] - mn1);
        mrow[0] = mn0; mrow[1] = mn1;
        lrow[0] *= al0; lrow[1] *= al1;
#pragma unroll
        for (int j = 0; j < 8; ++j) {
            o[j][0] *= al0; o[j][1] *= al0;
            o[j][2] *= al1; o[j][3] *= al1;
        }

        // exp -> half pairs (PV A-frags); l-sum over the half-rounded values
        unsigned pa[8][4];                  // [kc 0..7][a0..a3]
        float rs0 = 0.f, rs1 = 0.f;
#pragma unroll
        for (int nt = 0; nt < 16; ++nt) {
            float p0 = __expf(s[nt][0] - mrow[0]);
            float p1 = __expf(s[nt][1] - mrow[0]);
            float p2 = __expf(s[nt][2] - mrow[1]);
            float p3 = __expf(s[nt][3] - mrow[1]);
            unsigned lo = pack_h2(p0, p1);
            unsigned hi = pack_h2(p2, p3);
            int kc = nt >> 1;
            if ((nt & 1) == 0) { pa[kc][0] = lo; pa[kc][1] = hi; }
            else               { pa[kc][2] = lo; pa[kc][3] = hi; }
            __half2 hlo = *(__half2*)&lo, hhi = *(__half2*)&hi;
            rs0 += __low2float(hlo) + __high2float(hlo);
            rs1 += __low2float(hhi) + __high2float(hhi);
        }
        rs0 += __shfl_xor_sync(0xffffffffu, rs0, 1);
        rs0 += __shfl_xor_sync(0xffffffffu, rs0, 2);
        rs1 += __shfl_xor_sync(0xffffffffu, rs1, 1);
        rs1 += __shfl_xor_sync(0xffffffffu, rs1, 2);
        lrow[0] += rs0;
        lrow[1] += rs1;

        // O += P @ V over 8 k-chunks (128 keys)
#pragma unroll
        for (int jp = 0; jp < 4; ++jp)
#pragma unroll
            for (int kc = 0; kc < 8; ++kc) {
                unsigned bf[4];
                ldsm_x4(bf, &Vp[(jp * 16 + brow8 + l8) * VP2 + kc * 16 + bk8]);
                mma_f16(o[2 * jp],     pa[kc], bf[0], bf[1]);
                mma_f16(o[2 * jp + 1], pa[kc], bf[2], bf[3]);
            }
    }

    float inv0 = 1.f / lrow[0];
    float inv1 = 1.f / lrow[1];
    int r0 = q0 + w * 16 + gid;
#pragma unroll
    for (int j = 0; j < 8; ++j) {
        int col = h * NDH + j * 8 + 2 * tig;
        *(float2*)&out[((size_t)(b * NS + r0)) * NDV + col] =
            make_float2(o[j][0] * inv0, o[j][1] * inv0);
        *(float2*)&out[((size_t)(b * NS + r0 + 8)) * NDV + col] =
            make_float2(o[j][2] * inv1, o[j][3] * inv1);
    }
}

// ---------------------------------------------------------------------------
// Launch
// ---------------------------------------------------------------------------
extern "C" void kernel_launch(void* const* d_in, const int* in_sizes, int n_in,
                              void* d_out, int out_size) {
    const float* hid   = (const float*)d_in[0];
    const float* amask = (const float*)d_in[1];
    const float* txt   = (const float*)d_in[2];
    const float* tmask = (const float*)d_in[3];
    const float* Wq  = (const float*)d_in[4];
    const float* bq  = (const float*)d_in[5];
    const float* Wk  = (const float*)d_in[6];
    const float* bk  = (const float*)d_in[7];
    const float* Wv  = (const float*)d_in[8];
    const float* bv  = (const float*)d_in[9];
    const float* Wdq = (const float*)d_in[10];
    const float* bdq = (const float*)d_in[11];
    const float* Wdk = (const float*)d_in[12];
    const float* bdk = (const float*)d_in[13];
    float* out = (float*)d_out;

    cudaFuncSetAttribute(attn_kernel,
                         cudaFuncAttributeMaxDynamicSharedMemorySize,
                         ATTN_SMEM_BYTES);
    cudaFuncSetAttribute(qkv_kernel,
                         cudaFuncAttributeMaxDynamicSharedMemorySize,
                         QKV_SMEM_BYTES);

    wt_kernel<<<dim3(NDV / 32, NDV / 32, 3), dim3(32, 8)>>>(Wq, Wk, Wv);
    hidh_kernel<<<(NB * NS * NDV / 4 + 255) / 256, 256>>>(hid);
    pool_kernel<<<(NB * NDT + 255) / 256, 256>>>(txt, tmask);
    gate_kernel<<<dim3(NDV / 64, 2, NB), 256>>>(Wdq, bdq, Wdk, bdk);
    qkv_kernel<<<dim3(NDV / 128, (NB * NS) / 128, 3), 256, QKV_SMEM_BYTES>>>(
        bq, bk, bv);
    attn_kernel<<<dim3(NS / BQ, NB * NH), 128, ATTN_SMEM_BYTES>>>(amask, out);
}

// round 17
// speedup vs baseline: 1.0114x; 1.0114x over previous
#include <cuda_runtime.h>
#include <cuda_fp16.h>
#include <cstdint>
#include <cstddef>
#include <math.h>

// Problem constants
constexpr int NB  = 4;
constexpr int NS  = 2048;
constexpr int NDV = 1024;
constexpr int NH  = 16;
constexpr int NDH = 64;
constexpr int NT  = 64;
constexpr int NDT = 768;

// Scratch (device globals: allocation-free rule)
__device__ float  g_pool[NB * NDT];
__device__ float  g_gate_q[NB * NDV];
__device__ float  g_gate_k[NB * NDV];
__device__ __half g_wt[(size_t)3 * NDV * NDV];        // [z][nout][k] fp16
__device__ __half g_hidh[(size_t)NB * NS * NDV];      // hid as fp16
__device__ __half g_q[(size_t)NB * NH * NS * NDH];    // [bh][s][d]
__device__ __half g_k[(size_t)NB * NH * NS * NDH];    // [bh][s][d]
__device__ __half g_v[(size_t)NB * NH * NS * NDH];    // [bh][d][s] (TRANSPOSED)

// ---------------------------------------------------------------------------
// helpers
// ---------------------------------------------------------------------------
__device__ __forceinline__ void cp_async16(void* smem_dst, const void* gmem_src) {
    unsigned int s = (unsigned int)__cvta_generic_to_shared(smem_dst);
    asm volatile("cp.async.cg.shared.global [%0], [%1], 16;\n" :: "r"(s), "l"(gmem_src));
}
__device__ __forceinline__ void cp_commit() {
    asm volatile("cp.async.commit_group;\n");
}
template <int N>
__device__ __forceinline__ void cp_wait() {
    asm volatile("cp.async.wait_group %0;\n" :: "n"(N));
}
// D += A*B, m16n8k16 fp16 -> f32
__device__ __forceinline__ void mma_f16(float* c, const unsigned* a,
                                        unsigned b0, unsigned b1) {
    asm volatile(
        "mma.sync.aligned.m16n8k16.row.col.f32.f16.f16.f32 "
        "{%0,%1,%2,%3}, {%4,%5,%6,%7}, {%8,%9}, {%0,%1,%2,%3};\n"
        : "+f"(c[0]), "+f"(c[1]), "+f"(c[2]), "+f"(c[3])
        : "r"(a[0]), "r"(a[1]), "r"(a[2]), "r"(a[3]), "r"(b0), "r"(b1));
}
// ldmatrix x4 (b16)
__device__ __forceinline__ void ldsm_x4(unsigned* r, const void* p) {
    unsigned addr = (unsigned)__cvta_generic_to_shared(p);
    asm volatile("ldmatrix.sync.aligned.m8n8.x4.shared.b16 {%0,%1,%2,%3}, [%4];"
                 : "=r"(r[0]), "=r"(r[1]), "=r"(r[2]), "=r"(r[3]) : "r"(addr));
}
__device__ __forceinline__ unsigned pack_h2(float lo, float hi) {
    __half2 h = __floats2half2_rn(lo, hi);
    return *(unsigned*)&h;
}

// ---------------------------------------------------------------------------
// Kernel 0a: weight transpose+convert  g_wt[z][n][k] = fp16(W_z[k][n])
// ---------------------------------------------------------------------------
__global__ void wt_kernel(const float* __restrict__ Wq,
                          const float* __restrict__ Wk,
                          const float* __restrict__ Wv) {
    __shared__ float t[32][33];
    int z = blockIdx.z;
    const float* W = (z == 0) ? Wq : (z == 1) ? Wk : Wv;
    __half* out = g_wt + (size_t)z * NDV * NDV;
    int k0 = blockIdx.x * 32, n0 = blockIdx.y * 32;
    int x = threadIdx.x, y = threadIdx.y;       // 32 x 8
#pragma unroll
    for (int i = 0; i < 32; i += 8)
        t[y + i][x] = W[(size_t)(k0 + y + i) * NDV + n0 + x];
    __syncthreads();
#pragma unroll
    for (int i = 0; i < 32; i += 8)
        out[(size_t)(n0 + y + i) * NDV + k0 + x] = __float2half(t[x][y + i]);
}

// ---------------------------------------------------------------------------
// Kernel 0b: hid -> fp16
// ---------------------------------------------------------------------------
__global__ void hidh_kernel(const float* __restrict__ hid) {
    size_t i = ((size_t)blockIdx.x * blockDim.x + threadIdx.x) * 4;
    if (i >= (size_t)NB * NS * NDV) return;
    float4 v = *(const float4*)&hid[i];
    __half2 lo = __floats2half2_rn(v.x, v.y);
    __half2 hi = __floats2half2_rn(v.z, v.w);
    *(__half2*)&g_hidh[i]     = lo;
    *(__half2*)&g_hidh[i + 2] = hi;
}

// ---------------------------------------------------------------------------
// Kernel 1: masked-mean pool over text tokens.  pool[b,d]
// ---------------------------------------------------------------------------
__global__ void pool_kernel(const float* __restrict__ txt,
                            const float* __restrict__ tmask) {
    int i = blockIdx.x * blockDim.x + threadIdx.x;
    if (i >= NB * NDT) return;
    int b = i / NDT;
    int d = i - b * NDT;
    float s = 0.f, ms = 0.f;
#pragma unroll 8
    for (int t = 0; t < NT; ++t) {
        float mv = tmask[b * NT + t];
        s += txt[((size_t)(b * NT + t)) * NDT + d] * mv;
        ms += mv;
    }
    g_pool[i] = s / ms;
}

// ---------------------------------------------------------------------------
// Kernel 2: gates = 1 + sigmoid(pool @ Wd + bd).  (R15 parallel version)
// ---------------------------------------------------------------------------
__global__ void __launch_bounds__(256) gate_kernel(
        const float* __restrict__ Wdq, const float* __restrict__ bdq,
        const float* __restrict__ Wdk, const float* __restrict__ bdk) {
    __shared__ float ps[NDT];
    __shared__ float red[16][64];

    int bx    = blockIdx.x;
    int which = blockIdx.y;
    int b     = blockIdx.z;
    const float* W  = which ? Wdk : Wdq;
    const float* bb = which ? bdk : bdq;
    int tid = threadIdx.x;

    for (int i = tid; i < NDT; i += 256)
        ps[i] = g_pool[b * NDT + i];
    __syncthreads();

    int nq = tid & 15;
    int g  = tid >> 4;
    int n  = bx * 64 + nq * 4;
    float4 acc = make_float4(0.f, 0.f, 0.f, 0.f);
    int d0 = g * 48;
#pragma unroll 8
    for (int d = d0; d < d0 + 48; ++d) {
        float p = ps[d];
        float4 wv = *(const float4*)&W[(size_t)d * NDV + n];
        acc.x += p * wv.x; acc.y += p * wv.y;
        acc.z += p * wv.z; acc.w += p * wv.w;
    }
    *(float4*)&red[g][nq * 4] = acc;
    __syncthreads();

    if (tid < 64) {
        float s = 0.f;
#pragma unroll
        for (int g2 = 0; g2 < 16; ++g2) s += red[g2][tid];
        int col = bx * 64 + tid;
        float gate = 1.f + 1.f / (1.f + expf(-(s + bb[col])));
        (which ? g_gate_k : g_gate_q)[b * NDV + col] = gate;
    }
}

// ---------------------------------------------------------------------------
// Kernel 3: QKV projection via fp16 m16n8k16 mma + ldmatrix.  (unchanged)
// ---------------------------------------------------------------------------
constexpr int QKC  = 32;
constexpr int QPT  = 40;
constexpr int QNIT = NDV / QKC;
constexpr int QSTG = 3;
constexpr int QTILE = 128 * QPT;
constexpr int QKV_SMEM_BYTES = QSTG * 2 * QTILE * 2;   // 61440

__global__ void __launch_bounds__(256, 2) qkv_kernel(
        const float* __restrict__ bq,
        const float* __restrict__ bk,
        const float* __restrict__ bv) {
    extern __shared__ __half qsm[];
    __half* As = qsm;
    __half* Bs = qsm + QSTG * QTILE;

    int z = blockIdx.z;
    const __half* Wt = g_wt + (size_t)z * NDV * NDV;
    const float* bias = (z == 0) ? bq : (z == 1) ? bk : bv;
    const float* gate = (z == 0) ? g_gate_q : (z == 1) ? g_gate_k : nullptr;
    __half* out = (z == 0) ? g_q : (z == 1) ? g_k : g_v;

    int m0 = blockIdx.y * 128;
    int n0 = blockIdx.x * 128;
    int tid  = threadIdx.x;
    int warp = tid >> 5;
    int lane = tid & 31;
    int gid  = lane >> 2;
    int tig  = lane & 3;
    int wm = warp & 3;
    int wn = warp >> 2;
    int l16 = lane & 15;
    int l8  = lane & 7;
    int ahh = (lane >> 4) * 8;
    int brow8 = ((lane >> 4) & 1) * 8;
    int bk8   = ((lane >> 3) & 1) * 8;

    auto issue = [&](int c, int st) {
#pragma unroll
        for (int u = 0; u < 2; ++u) {
            int idx = tid * 2 + u;
            int row = idx >> 2;
            int c16 = idx & 3;
            cp_async16(&As[(size_t)st * QTILE + row * QPT + c16 * 8],
                       &g_hidh[(size_t)(m0 + row) * NDV + c * QKC + c16 * 8]);
            cp_async16(&Bs[(size_t)st * QTILE + row * QPT + c16 * 8],
                       &Wt[(size_t)(n0 + row) * NDV + c * QKC + c16 * 8]);
        }
        cp_commit();
    };

    float c[2][8][4];
#pragma unroll
    for (int mt = 0; mt < 2; ++mt)
#pragma unroll
        for (int nt = 0; nt < 8; ++nt)
#pragma unroll
            for (int r = 0; r < 4; ++r) c[mt][nt][r] = 0.f;

    issue(0, 0);
    issue(1, 1);

    int st = 0;
    for (int it = 0; it < QNIT; ++it) {
        cp_wait<1>();
        __syncthreads();
        int st2 = st + 2; if (st2 >= QSTG) st2 -= QSTG;
        if (it + 2 < QNIT) issue(it + 2, st2);

        const __half* Ap = &As[(size_t)st * QTILE];
        const __half* Bp = &Bs[(size_t)st * QTILE];

        unsigned a[2][2][4];
#pragma unroll
        for (int mt = 0; mt < 2; ++mt)
#pragma unroll
            for (int ks = 0; ks < 2; ++ks)
                ldsm_x4(a[mt][ks],
                        &Ap[(wm * 32 + mt * 16 + l16) * QPT + ks * 16 + ahh]);

        unsigned bfr[4][2][4];
#pragma unroll
        for (int ntp = 0; ntp < 4; ++ntp)
#pragma unroll
            for (int ks = 0; ks < 2; ++ks)
                ldsm_x4(bfr[ntp][ks],
                        &Bp[(wn * 64 + ntp * 16 + brow8 + l8) * QPT + ks * 16 + bk8]);

#pragma unroll
        for (int mt = 0; mt < 2; ++mt)
#pragma unroll
            for (int ntp = 0; ntp < 4; ++ntp)
#pragma unroll
                for (int ks = 0; ks < 2; ++ks) {
                    mma_f16(c[mt][2 * ntp],     a[mt][ks], bfr[ntp][ks][0], bfr[ntp][ks][1]);
                    mma_f16(c[mt][2 * ntp + 1], a[mt][ks], bfr[ntp][ks][2], bfr[ntp][ks][3]);
                }

        if (++st == QSTG) st = 0;
    }

    int b = m0 >> 11;
#pragma unroll
    for (int mt = 0; mt < 2; ++mt) {
        int tok  = m0 + wm * 32 + mt * 16 + gid;
        int srow = tok & (NS - 1);
#pragma unroll
        for (int nt = 0; nt < 8; ++nt) {
            int col = n0 + wn * 64 + nt * 8 + 2 * tig;
            float g0 = gate ? gate[b * NDV + col]     : 1.f;
            float g1 = gate ? gate[b * NDV + col + 1] : 1.f;
            float b0v = bias[col], b1v = bias[col + 1];
            float v00 = (c[mt][nt][0] + b0v) * g0;
            float v01 = (c[mt][nt][1] + b1v) * g1;
            float v10 = (c[mt][nt][2] + b0v) * g0;
            float v11 = (c[mt][nt][3] + b1v) * g1;
            int h = col >> 6, d = col & 63;
            if (z == 2) {
                __half* p = out + ((size_t)(b * NH + h) * NDH + d) * NS;
                p[srow]          = __float2half(v00);
                p[NS + srow]     = __float2half(v01);
                p[srow + 8]      = __float2half(v10);
                p[NS + srow + 8] = __float2half(v11);
            } else {
                __half* p = out + ((size_t)(b * NH + h) * NS) * NDH + d;
                *(__half2*)&p[(size_t)srow * NDH] = __floats2half2_rn(v00, v01);
                *(__half2*)&p[(size_t)(srow + 8) * NDH] = __floats2half2_rn(v10, v11);
            }
        }
    }
}

// ---------------------------------------------------------------------------
// Kernel 4: flash attention, fp16 m16n8k16.  R15 config (BK=64) with
// occupancy raised to 4 blocks/SM (16 warps = 4/SMSP) to absorb HMMA
// dependency gaps.  BQ=64, 4 warps x 16 q-rows, 2-stage cp.async.
// ---------------------------------------------------------------------------
constexpr int BQ = 64;
constexpr int BK = 64;
constexpr int NTILE = NS / BK;          // 32
constexpr int KP = 72;                  // pitch halves
constexpr int VP = 72;
constexpr int ATTN_SMEM_BYTES = (2 * BK * KP + 2 * NDH * VP) * 2;   // 36864

__global__ void __launch_bounds__(128, 4) attn_kernel(
        const float* __restrict__ amask, float* __restrict__ out) {
    extern __shared__ __half hsm[];
    __half* Ks = hsm;                         // [2][BK][KP]  token-major
    __half* Vs = hsm + 2 * BK * KP;           // [2][NDH][VP] d-major (V^T)

    int bh = blockIdx.y;
    int b  = bh >> 4;
    int h  = bh & 15;
    int q0 = blockIdx.x * BQ;
    int tid  = threadIdx.x;
    int w    = tid >> 5;
    int lane = tid & 31;
    int gid  = lane >> 2;
    int tig  = lane & 3;
    int l8  = lane & 7;
    int brow8 = ((lane >> 4) & 1) * 8;
    int bk8   = ((lane >> 3) & 1) * 8;

    const __half* Qg = g_q + (size_t)bh * NS * NDH;
    const __half* Kg = g_k + (size_t)bh * NS * NDH;
    const __half* Vg = g_v + (size_t)bh * NDH * NS;   // [d][s]

    auto issue_kv = [&](int t0, int st) {
#pragma unroll
        for (int u = 0; u < 8; ++u) {
            int idx = tid + u * 128;         // 0..1023: K chunks then V chunks
            int is_v = idx >> 9;
            int r2   = (idx & 511) >> 3;     // 0..63
            int c16  = idx & 7;
            if (!is_v)
                cp_async16(&Ks[(size_t)st * BK * KP + r2 * KP + c16 * 8],
                           &Kg[(size_t)(t0 + r2) * NDH + c16 * 8]);
            else
                cp_async16(&Vs[(size_t)st * NDH * VP + r2 * VP + c16 * 8],
                           &Vg[(size_t)r2 * NS + t0 + c16 * 8]);
        }
        cp_commit();
    };

    issue_kv(0, 0);

    // Q A-frags from gmem fp16 (4 k-chunks of 16)
    unsigned a[4][4];
    {
        const __half* Qr0 = Qg + (size_t)(q0 + w * 16 + gid) * NDH;
        const __half* Qr8 = Qr0 + 8 * NDH;
#pragma unroll
        for (int kc = 0; kc < 4; ++kc) {
            a[kc][0] = *(const unsigned*)&Qr0[kc * 16 + 2 * tig];
            a[kc][1] = *(const unsigned*)&Qr8[kc * 16 + 2 * tig];
            a[kc][2] = *(const unsigned*)&Qr0[kc * 16 + 8 + 2 * tig];
            a[kc][3] = *(const unsigned*)&Qr8[kc * 16 + 8 + 2 * tig];
        }
    }

    float o[8][4];
#pragma unroll
    for (int j = 0; j < 8; ++j)
#pragma unroll
        for (int r = 0; r < 4; ++r) o[j][r] = 0.f;
    float mrow[2] = {-1e30f, -1e30f};
    float lrow[2] = {0.f, 0.f};

    for (int it = 0; it < NTILE; ++it) {
        cp_wait<0>();
        __syncthreads();
        if (it + 1 < NTILE) issue_kv((it + 1) * BK, (it + 1) & 1);
        int st = it & 1;
        const __half* Kp = &Ks[(size_t)st * BK * KP];
        const __half* Vp = &Vs[(size_t)st * NDH * VP];
        int t0 = it * BK;

        // S = Q @ K^T
        float s[8][4];
#pragma unroll
        for (int nt = 0; nt < 8; ++nt)
            s[nt][0] = s[nt][1] = s[nt][2] = s[nt][3] = 0.f;
#pragma unroll
        for (int ntp = 0; ntp < 4; ++ntp)
#pragma unroll
            for (int kc = 0; kc < 4; ++kc) {
                unsigned bf[4];
                ldsm_x4(bf, &Kp[(ntp * 16 + brow8 + l8) * KP + kc * 16 + bk8]);
                mma_f16(s[2 * ntp],     a[kc], bf[0], bf[1]);
                mma_f16(s[2 * ntp + 1], a[kc], bf[2], bf[3]);
            }

        // scale + mask + online softmax
        float mt0 = -1e30f, mt1 = -1e30f;
#pragma unroll
        for (int nt = 0; nt < 8; ++nt) {
            float2 mk = *(const float2*)&amask[b * NS + t0 + nt * 8 + 2 * tig];
            s[nt][0] = fmaf(s[nt][0], 0.125f, mk.x);
            s[nt][1] = fmaf(s[nt][1], 0.125f, mk.y);
            s[nt][2] = fmaf(s[nt][2], 0.125f, mk.x);
            s[nt][3] = fmaf(s[nt][3], 0.125f, mk.y);
            mt0 = fmaxf(mt0, fmaxf(s[nt][0], s[nt][1]));
            mt1 = fmaxf(mt1, fmaxf(s[nt][2], s[nt][3]));
        }
        mt0 = fmaxf(mt0, __shfl_xor_sync(0xffffffffu, mt0, 1));
        mt0 = fmaxf(mt0, __shfl_xor_sync(0xffffffffu, mt0, 2));
        mt1 = fmaxf(mt1, __shfl_xor_sync(0xffffffffu, mt1, 1));
        mt1 = fmaxf(mt1, __shfl_xor_sync(0xffffffffu, mt1, 2));

        float mn0 = fmaxf(mrow[0], mt0);
        float mn1 = fmaxf(mrow[1], mt1);
        float al0 = __expf(mrow[0] - mn0);
        float al1 = __expf(mrow[1] - mn1);
        mrow[0] = mn0; mrow[1] = mn1;
        lrow[0] *= al0; lrow[1] *= al1;
#pragma unroll
        for (int j = 0; j < 8; ++j) {
            o[j][0] *= al0; o[j][1] *= al0;
            o[j][2] *= al1; o[j][3] *= al1;
        }

        // exp -> half pairs (PV A-frags); l-sum over the half-rounded values
        unsigned pa[4][4];
        float rs0 = 0.f, rs1 = 0.f;
#pragma unroll
        for (int nt = 0; nt < 8; ++nt) {
            float p0 = __expf(s[nt][0] - mrow[0]);
            float p1 = __expf(s[nt][1] - mrow[0]);
            float p2 = __expf(s[nt][2] - mrow[1]);
            float p3 = __expf(s[nt][3] - mrow[1]);
            unsigned lo = pack_h2(p0, p1);
            unsigned hi = pack_h2(p2, p3);
            int kc = nt >> 1;
            if ((nt & 1) == 0) { pa[kc][0] = lo; pa[kc][1] = hi; }
            else               { pa[kc][2] = lo; pa[kc][3] = hi; }
            __half2 hlo = *(__half2*)&lo, hhi = *(__half2*)&hi;
            rs0 += __low2float(hlo) + __high2float(hlo);
            rs1 += __low2float(hhi) + __high2float(hhi);
        }
        rs0 += __shfl_xor_sync(0xffffffffu, rs0, 1);
        rs0 += __shfl_xor_sync(0xffffffffu, rs0, 2);
        rs1 += __shfl_xor_sync(0xffffffffu, rs1, 1);
        rs1 += __shfl_xor_sync(0xffffffffu, rs1, 2);
        lrow[0] += rs0;
        lrow[1] += rs1;

        // O += P @ V
#pragma unroll
        for (int jp = 0; jp < 4; ++jp)
#pragma unroll
            for (int kc = 0; kc < 4; ++kc) {
                unsigned bf[4];
                ldsm_x4(bf, &Vp[(jp * 16 + brow8 + l8) * VP + kc * 16 + bk8]);
                mma_f16(o[2 * jp],     pa[kc], bf[0], bf[1]);
                mma_f16(o[2 * jp + 1], pa[kc], bf[2], bf[3]);
            }
    }

    float inv0 = 1.f / lrow[0];
    float inv1 = 1.f / lrow[1];
    int r0 = q0 + w * 16 + gid;
#pragma unroll
    for (int j = 0; j < 8; ++j) {
        int col = h * NDH + j * 8 + 2 * tig;
        *(float2*)&out[((size_t)(b * NS + r0)) * NDV + col] =
            make_float2(o[j][0] * inv0, o[j][1] * inv0);
        *(float2*)&out[((size_t)(b * NS + r0 + 8)) * NDV + col] =
            make_float2(o[j][2] * inv1, o[j][3] * inv1);
    }
}

// ---------------------------------------------------------------------------
// Launch
// ---------------------------------------------------------------------------
extern "C" void kernel_launch(void* const* d_in, const int* in_sizes, int n_in,
                              void* d_out, int out_size) {
    const float* hid   = (const float*)d_in[0];
    const float* amask = (const float*)d_in[1];
    const float* txt   = (const float*)d_in[2];
    const float* tmask = (const float*)d_in[3];
    const float* Wq  = (const float*)d_in[4];
    const float* bq  = (const float*)d_in[5];
    const float* Wk  = (const float*)d_in[6];
    const float* bk  = (const float*)d_in[7];
    const float* Wv  = (const float*)d_in[8];
    const float* bv  = (const float*)d_in[9];
    const float* Wdq = (const float*)d_in[10];
    const float* bdq = (const float*)d_in[11];
    const float* Wdk = (const float*)d_in[12];
    const float* bdk = (const float*)d_in[13];
    float* out = (float*)d_out;

    cudaFuncSetAttribute(attn_kernel,
                         cudaFuncAttributeMaxDynamicSharedMemorySize,
                         ATTN_SMEM_BYTES);
    cudaFuncSetAttribute(qkv_kernel,
                         cudaFuncAttributeMaxDynamicSharedMemorySize,
                         QKV_SMEM_BYTES);

    wt_kernel<<<dim3(NDV / 32, NDV / 32, 3), dim3(32, 8)>>>(Wq, Wk, Wv);
    hidh_kernel<<<(NB * NS * NDV / 4 + 255) / 256, 256>>>(hid);
    pool_kernel<<<(NB * NDT + 255) / 256, 256>>>(txt, tmask);
    gate_kernel<<<dim3(NDV / 64, 2, NB), 256>>>(Wdq, bdq, Wdk, bdk);
    qkv_kernel<<<dim3(NDV / 128, (NB * NS) / 128, 3), 256, QKV_SMEM_BYTES>>>(
        bq, bk, bv);
    attn_kernel<<<dim3(NS / BQ, NB * NH), 128, ATTN_SMEM_BYTES>>>(amask, out);
}